// round 16
// baseline (speedup 1.0000x reference)
#include <cuda_runtime.h>
#include <cuda_bf16.h>
#include <math_constants.h>
#include <cstdint>

#define Bc   64
#define Tc   256
#define Cn   64
#define Hn   8
#define HSn  8
#define Ln   10
#define DFF  256
#define VOC  8000
#define BT   (Bc*Tc)
#define EPSF 1e-5f

#define SZ_XC (BT*Cn)
#define SZ_FF (BT*DFF)
__device__ float g_scratch[SZ_XC*6 + SZ_FF];
__device__ __nv_bfloat16 g_hhi[BT*Cn];
__device__ __nv_bfloat16 g_hlo[BT*Cn];
__device__ __nv_bfloat16 g_wthi[VOC*Cn];   // transposed: [n][k]
__device__ __nv_bfloat16 g_wtlo[VOC*Cn];

typedef unsigned long long u64;

__device__ __forceinline__ u64 pk2(float x, float y){
    u64 r; asm("mov.b64 %0,{%1,%2};" : "=l"(r) : "f"(x), "f"(y)); return r;
}
__device__ __forceinline__ void upk2(u64 p, float& x, float& y){
    asm("mov.b64 {%0,%1},%2;" : "=f"(x), "=f"(y) : "l"(p));
}
__device__ __forceinline__ void ffma2(u64& a, u64 b, u64 c){
    asm("fma.rn.f32x2 %0,%1,%2,%0;" : "+l"(a) : "l"(b), "l"(c));
}

// ===========================================================================
// Layer GEMM (exact R3 structure: best measured). BM=128, BN=64, BK=16,
// 128 threads, 8x8 thread tile packed as 4x8 f32x2 row-pair accumulators.
// ===========================================================================
template<int EPI>
__device__ __forceinline__ void gemm_body(
    const float* __restrict__ A, const float* __restrict__ W,
    const float* __restrict__ bias, const float* __restrict__ res,
    float* __restrict__ Cout, float* __restrict__ Hout,
    const float* __restrict__ lng, const float* __restrict__ lnb,
    int N, int K)
{
    __shared__ float As[16][130];
    __shared__ float Ws[16][64];
    const int tid  = threadIdx.x;
    const int row0 = blockIdx.y * 128;
    const int col0 = blockIdx.x * 64;
    const int tx   = tid & 7;
    const int ty   = tid >> 3;

    u64 acc[4][8];
    #pragma unroll
    for (int i = 0; i < 4; i++)
        #pragma unroll
        for (int j = 0; j < 8; j++) acc[i][j] = 0ull;

    for (int k0 = 0; k0 < K; k0 += 16) {
        #pragma unroll
        for (int v = 0; v < 4; v++) {
            int idx = tid + v * 128;
            int m   = idx >> 2;
            int k4  = (idx & 3) * 4;
            float4 t = *(const float4*)&A[(row0 + m) * K + k0 + k4];
            As[k4+0][m] = t.x; As[k4+1][m] = t.y; As[k4+2][m] = t.z; As[k4+3][m] = t.w;
        }
        #pragma unroll
        for (int v = 0; v < 2; v++) {
            int idx = tid + v * 128;
            int k   = idx >> 4;
            int n4  = (idx & 15) * 4;
            *(float4*)&Ws[k][n4] = *(const float4*)&W[(k0 + k) * N + col0 + n4];
        }
        __syncthreads();
        #pragma unroll
        for (int k = 0; k < 16; k++) {
            u64 a2[4];
            #pragma unroll
            for (int i = 0; i < 4; i++)
                a2[i] = *(const u64*)&As[k][ty * 8 + i * 2];
            u64 bd[8];
            {
                float4 b0 = *(const float4*)&Ws[k][tx * 8];
                float4 b1 = *(const float4*)&Ws[k][tx * 8 + 4];
                bd[0]=pk2(b0.x,b0.x); bd[1]=pk2(b0.y,b0.y); bd[2]=pk2(b0.z,b0.z); bd[3]=pk2(b0.w,b0.w);
                bd[4]=pk2(b1.x,b1.x); bd[5]=pk2(b1.y,b1.y); bd[6]=pk2(b1.z,b1.z); bd[7]=pk2(b1.w,b1.w);
            }
            #pragma unroll
            for (int i = 0; i < 4; i++)
                #pragma unroll
                for (int j = 0; j < 8; j++)
                    ffma2(acc[i][j], a2[i], bd[j]);
        }
        __syncthreads();
    }

    float bj[8];
    #pragma unroll
    for (int j = 0; j < 8; j++) bj[j] = bias ? bias[col0 + tx * 8 + j] : 0.0f;

    float gj[8], bb[8];
    if (EPI == 2) {
        float4 g0 = *(const float4*)&lng[tx*8], g1 = *(const float4*)&lng[tx*8+4];
        float4 e0 = *(const float4*)&lnb[tx*8], e1 = *(const float4*)&lnb[tx*8+4];
        gj[0]=g0.x; gj[1]=g0.y; gj[2]=g0.z; gj[3]=g0.w; gj[4]=g1.x; gj[5]=g1.y; gj[6]=g1.z; gj[7]=g1.w;
        bb[0]=e0.x; bb[1]=e0.y; bb[2]=e0.z; bb[3]=e0.w; bb[4]=e1.x; bb[5]=e1.y; bb[6]=e1.z; bb[7]=e1.w;
    }

    #pragma unroll
    for (int i2 = 0; i2 < 4; i2++) {
        float lo[8], hi[8];
        #pragma unroll
        for (int j = 0; j < 8; j++) {
            upk2(acc[i2][j], lo[j], hi[j]);
            lo[j] += bj[j]; hi[j] += bj[j];
        }
        int r0 = row0 + ty * 8 + i2 * 2;
        int cb = col0 + tx * 8;

        if (EPI == 1) {
            #pragma unroll
            for (int j = 0; j < 8; j++) { lo[j] = fmaxf(lo[j], 0.f); hi[j] = fmaxf(hi[j], 0.f); }
        }
        if (EPI == 2) {
            float4 r0a = *(const float4*)&res[r0*64 + cb];
            float4 r0b = *(const float4*)&res[r0*64 + cb + 4];
            float4 r1a = *(const float4*)&res[(r0+1)*64 + cb];
            float4 r1b = *(const float4*)&res[(r0+1)*64 + cb + 4];
            lo[0]+=r0a.x; lo[1]+=r0a.y; lo[2]+=r0a.z; lo[3]+=r0a.w;
            lo[4]+=r0b.x; lo[5]+=r0b.y; lo[6]+=r0b.z; lo[7]+=r0b.w;
            hi[0]+=r1a.x; hi[1]+=r1a.y; hi[2]+=r1a.z; hi[3]+=r1a.w;
            hi[4]+=r1b.x; hi[5]+=r1b.y; hi[6]+=r1b.z; hi[7]+=r1b.w;

            float s1l=0.f, s2l=0.f, s1h=0.f, s2h=0.f;
            #pragma unroll
            for (int j = 0; j < 8; j++) {
                s1l += lo[j]; s2l += lo[j]*lo[j];
                s1h += hi[j]; s2h += hi[j]*hi[j];
            }
            #pragma unroll
            for (int o = 1; o < 8; o <<= 1) {
                s1l += __shfl_xor_sync(0xFFFFFFFFu, s1l, o);
                s2l += __shfl_xor_sync(0xFFFFFFFFu, s2l, o);
                s1h += __shfl_xor_sync(0xFFFFFFFFu, s1h, o);
                s2h += __shfl_xor_sync(0xFFFFFFFFu, s2h, o);
            }
            float mul = s1l * (1.f/64.f);
            float muh = s1h * (1.f/64.f);
            float rsl = rsqrtf(s2l * (1.f/64.f) - mul*mul + EPSF);
            float rsh = rsqrtf(s2h * (1.f/64.f) - muh*muh + EPSF);
            *(float4*)&Cout[r0*64+cb]       = make_float4(lo[0],lo[1],lo[2],lo[3]);
            *(float4*)&Cout[r0*64+cb+4]     = make_float4(lo[4],lo[5],lo[6],lo[7]);
            *(float4*)&Cout[(r0+1)*64+cb]   = make_float4(hi[0],hi[1],hi[2],hi[3]);
            *(float4*)&Cout[(r0+1)*64+cb+4] = make_float4(hi[4],hi[5],hi[6],hi[7]);
            float hl[8], hh[8];
            #pragma unroll
            for (int j = 0; j < 8; j++) {
                hl[j] = (lo[j]-mul)*rsl*gj[j] + bb[j];
                hh[j] = (hi[j]-muh)*rsh*gj[j] + bb[j];
            }
            *(float4*)&Hout[r0*64+cb]       = make_float4(hl[0],hl[1],hl[2],hl[3]);
            *(float4*)&Hout[r0*64+cb+4]     = make_float4(hl[4],hl[5],hl[6],hl[7]);
            *(float4*)&Hout[(r0+1)*64+cb]   = make_float4(hh[0],hh[1],hh[2],hh[3]);
            *(float4*)&Hout[(r0+1)*64+cb+4] = make_float4(hh[4],hh[5],hh[6],hh[7]);
        } else {
            *(float4*)&Cout[r0*N+cb]       = make_float4(lo[0],lo[1],lo[2],lo[3]);
            *(float4*)&Cout[r0*N+cb+4]     = make_float4(lo[4],lo[5],lo[6],lo[7]);
            *(float4*)&Cout[(r0+1)*N+cb]   = make_float4(hi[0],hi[1],hi[2],hi[3]);
            *(float4*)&Cout[(r0+1)*N+cb+4] = make_float4(hi[4],hi[5],hi[6],hi[7]);
        }
    }
}

template<int EPI>
__global__ void __launch_bounds__(128)
gemm_k(const float* __restrict__ A, const float* __restrict__ W,
       const float* __restrict__ bias, const float* __restrict__ res,
       float* __restrict__ Cout, float* __restrict__ Hout,
       const float* __restrict__ lng, const float* __restrict__ lnb,
       int N, int K)
{
    gemm_body<EPI>(A, W, bias, res, Cout, Hout, lng, lnb, N, K);
}

__global__ void __launch_bounds__(128)
qkv_k(const float* __restrict__ A,
      const float* __restrict__ wq, const float* __restrict__ wk, const float* __restrict__ wv,
      float* __restrict__ q, float* __restrict__ k, float* __restrict__ v)
{
    const float* W = (blockIdx.z == 0) ? wq : (blockIdx.z == 1) ? wk : wv;
    float*       O = (blockIdx.z == 0) ? q  : (blockIdx.z == 1) ? k  : v;
    gemm_body<0>(A, W, nullptr, nullptr, O, nullptr, nullptr, nullptr, 64, 64);
}

// ===========================================================================
// Embedding + first LayerNorm (R3)
// ===========================================================================
__global__ void __launch_bounds__(256)
embed_ln_k(const int* __restrict__ idx, const float* __restrict__ tok,
           const float* __restrict__ pos, const float* __restrict__ g,
           const float* __restrict__ b, float* __restrict__ x, float* __restrict__ h)
{
    int row  = blockIdx.x * 8 + (threadIdx.x >> 5);
    int lane = threadIdx.x & 31;
    int t    = row & (Tc - 1);
    int tr   = idx[row];
    float v0 = tok[tr*Cn + lane]      + pos[t*Cn + lane];
    float v1 = tok[tr*Cn + lane + 32] + pos[t*Cn + lane + 32];
    float sum = v0 + v1;
    #pragma unroll
    for (int o = 16; o; o >>= 1) sum += __shfl_xor_sync(0xFFFFFFFFu, sum, o);
    float mu = sum * (1.f/64.f);
    float d0 = v0 - mu, d1 = v1 - mu;
    float vs = d0*d0 + d1*d1;
    #pragma unroll
    for (int o = 16; o; o >>= 1) vs += __shfl_xor_sync(0xFFFFFFFFu, vs, o);
    float r = rsqrtf(vs * (1.f/64.f) + EPSF);
    x[row*Cn + lane]      = v0;
    x[row*Cn + lane + 32] = v1;
    h[row*Cn + lane]      = d0*r*g[lane]    + b[lane];
    h[row*Cn + lane + 32] = d1*r*g[lane+32] + b[lane+32];
}

// ===========================================================================
// Attention v2 (R13 winner): block per (b,h), 256 threads = 256 query rows.
// Thread t owns row t and loops j=0..t; all lanes read the SAME ks[j]/vs[j]
// (smem broadcast, conflict-free) -> no crossbar serialization, no shuffles.
// ===========================================================================
__global__ void __launch_bounds__(256)
attn_kernel(const float* __restrict__ q, const float* __restrict__ kk,
            const float* __restrict__ vv, float* __restrict__ oo)
{
    int bh = blockIdx.x;
    int b  = bh >> 3;
    int h  = bh & 7;
    __shared__ float ks[Tc][8];
    __shared__ float vs[Tc][8];

    int tid  = threadIdx.x;
    int base = b * Tc * Cn + h * HSn;

    {
        float4 a = *(const float4*)&kk[base + tid*Cn];
        float4 c = *(const float4*)&kk[base + tid*Cn + 4];
        *(float4*)&ks[tid][0] = a; *(float4*)&ks[tid][4] = c;
        a = *(const float4*)&vv[base + tid*Cn];
        c = *(const float4*)&vv[base + tid*Cn + 4];
        *(float4*)&vs[tid][0] = a; *(float4*)&vs[tid][4] = c;
    }
    __syncthreads();

    const int row = tid;
    float qd[8];
    {
        float4 a = *(const float4*)&q[base + row*Cn];
        float4 c = *(const float4*)&q[base + row*Cn + 4];
        qd[0]=a.x*0.125f; qd[1]=a.y*0.125f; qd[2]=a.z*0.125f; qd[3]=a.w*0.125f;
        qd[4]=c.x*0.125f; qd[5]=c.y*0.125f; qd[6]=c.z*0.125f; qd[7]=c.w*0.125f;
    }

    float s = 0.0f;
    float o[8];
    #pragma unroll
    for (int d = 0; d < 8; d++) o[d] = 0.0f;

    #pragma unroll 2
    for (int j = 0; j <= row; j++) {
        float4 ka = *(const float4*)&ks[j][0];
        float4 kb = *(const float4*)&ks[j][4];
        float sc = qd[0]*ka.x;
        sc = fmaf(qd[1], ka.y, sc);
        sc = fmaf(qd[2], ka.z, sc);
        sc = fmaf(qd[3], ka.w, sc);
        sc = fmaf(qd[4], kb.x, sc);
        sc = fmaf(qd[5], kb.y, sc);
        sc = fmaf(qd[6], kb.z, sc);
        sc = fmaf(qd[7], kb.w, sc);
        float e = __expf(sc);
        s += e;
        float4 va = *(const float4*)&vs[j][0];
        float4 vb = *(const float4*)&vs[j][4];
        o[0] = fmaf(e, va.x, o[0]);
        o[1] = fmaf(e, va.y, o[1]);
        o[2] = fmaf(e, va.z, o[2]);
        o[3] = fmaf(e, va.w, o[3]);
        o[4] = fmaf(e, vb.x, o[4]);
        o[5] = fmaf(e, vb.y, o[5]);
        o[6] = fmaf(e, vb.z, o[6]);
        o[7] = fmaf(e, vb.w, o[7]);
    }

    float inv = 1.0f / s;
    *(float4*)&oo[base + row*Cn]     = make_float4(o[0]*inv, o[1]*inv, o[2]*inv, o[3]*inv);
    *(float4*)&oo[base + row*Cn + 4] = make_float4(o[4]*inv, o[5]*inv, o[6]*inv, o[7]*inv);
}

// ===========================================================================
// bf16 hi/lo converts for the tensor-core head
// ===========================================================================
__global__ void __launch_bounds__(256)
conv_h_k(const float* __restrict__ h, __nv_bfloat16* __restrict__ hhi,
         __nv_bfloat16* __restrict__ hlo)
{
    int i = blockIdx.x * 256 + threadIdx.x;
    float x = h[i];
    __nv_bfloat16 hb = __float2bfloat16_rn(x);
    hhi[i] = hb;
    hlo[i] = __float2bfloat16_rn(x - __bfloat162float(hb));
}

// w_head [K=64, VOC] fp32 -> transposed bf16 hi/lo [VOC][64]
__global__ void __launch_bounds__(256)
conv_w_k(const float* __restrict__ w, __nv_bfloat16* __restrict__ whi,
         __nv_bfloat16* __restrict__ wlo)
{
    int i = blockIdx.x * 256 + threadIdx.x;   // over VOC*64
    int n = i >> 6;
    int k = i & 63;
    float x = w[k * VOC + n];
    __nv_bfloat16 hb = __float2bfloat16_rn(x);
    whi[i] = hb;
    wlo[i] = __float2bfloat16_rn(x - __bfloat162float(hb));
}

// ===========================================================================
// Tensor-core head GEMM via mma.sync (plain sm_103 PTX; no tcgen05).
// out[16384, VOC] = h @ w_head + b_head.
// CTA = 256 thr / 8 warps, tile M=128 x N=64, K=64 resident in smem.
// D = Ahi*Bhi + Ahi*Blo + Alo*Bhi (bf16 hi/lo split, ~2^-16 rel err).
// A stored [m][k], B stored [n][k] (row-major n x k feeds B frags directly).
// ===========================================================================
#define HSTRIDE 72   // bf16 elems per smem row (144B: conflict-free ldmatrix)
#define SM_HEAD_BYTES ((128 + 128 + 64 + 64) * HSTRIDE * 2)   // 55296

__device__ __forceinline__ uint32_t s2u(const void* p){
    uint32_t a;
    asm("{ .reg .u64 t; cvta.to.shared.u64 t, %1; cvt.u32.u64 %0, t; }" : "=r"(a) : "l"(p));
    return a;
}
__device__ __forceinline__ void ldsm4(uint32_t& r0, uint32_t& r1, uint32_t& r2, uint32_t& r3, uint32_t addr){
    asm volatile("ldmatrix.sync.aligned.m8n8.x4.shared.b16 {%0,%1,%2,%3}, [%4];"
        : "=r"(r0), "=r"(r1), "=r"(r2), "=r"(r3) : "r"(addr));
}
__device__ __forceinline__ void ldsm2(uint32_t& r0, uint32_t& r1, uint32_t addr){
    asm volatile("ldmatrix.sync.aligned.m8n8.x2.shared.b16 {%0,%1}, [%2];"
        : "=r"(r0), "=r"(r1) : "r"(addr));
}
__device__ __forceinline__ void mma16816(float* d, uint32_t a0, uint32_t a1, uint32_t a2, uint32_t a3,
                                         uint32_t b0, uint32_t b1){
    asm volatile("mma.sync.aligned.m16n8k16.row.col.f32.bf16.bf16.f32 "
        "{%0,%1,%2,%3}, {%4,%5,%6,%7}, {%8,%9}, {%0,%1,%2,%3};"
        : "+f"(d[0]), "+f"(d[1]), "+f"(d[2]), "+f"(d[3])
        : "r"(a0), "r"(a1), "r"(a2), "r"(a3), "r"(b0), "r"(b1));
}

__global__ void __launch_bounds__(256)
head_mma_k(const __nv_bfloat16* __restrict__ ahi, const __nv_bfloat16* __restrict__ alo,
           const __nv_bfloat16* __restrict__ bhi, const __nv_bfloat16* __restrict__ blo,
           const float* __restrict__ bias, float* __restrict__ out)
{
    extern __shared__ __nv_bfloat16 sm[];
    __nv_bfloat16* sAhi = sm;
    __nv_bfloat16* sAlo = sm + 128 * HSTRIDE;
    __nv_bfloat16* sBhi = sm + 256 * HSTRIDE;
    __nv_bfloat16* sBlo = sm + 320 * HSTRIDE;

    const int tid  = threadIdx.x;
    const int row0 = blockIdx.y * 128;
    const int col0 = blockIdx.x * 64;

    // Stage A (128 x 64 bf16, hi+lo)
    #pragma unroll
    for (int v = 0; v < 4; v++) {
        int i = tid + v * 256;          // over 128*8 uint4 chunks
        int r = i >> 3, c = (i & 7) * 8;
        *(uint4*)&sAhi[r * HSTRIDE + c] = *(const uint4*)&ahi[(row0 + r) * 64 + c];
        *(uint4*)&sAlo[r * HSTRIDE + c] = *(const uint4*)&alo[(row0 + r) * 64 + c];
    }
    // Stage B (64 x 64 bf16, hi+lo), stored [n][k]
    #pragma unroll
    for (int v = 0; v < 2; v++) {
        int i = tid + v * 256;          // over 64*8 chunks
        int r = i >> 3, c = (i & 7) * 8;
        *(uint4*)&sBhi[r * HSTRIDE + c] = *(const uint4*)&bhi[(col0 + r) * 64 + c];
        *(uint4*)&sBlo[r * HSTRIDE + c] = *(const uint4*)&blo[(col0 + r) * 64 + c];
    }
    __syncthreads();

    const int warp = tid >> 5;
    const int lane = tid & 31;
    const int m0 = (warp & 3) * 32;     // warp rows m0..m0+31
    const int n0 = (warp >> 2) * 32;    // warp cols n0..n0+31

    const uint32_t baseAhi = s2u(sAhi);
    const uint32_t baseAlo = s2u(sAlo);
    const uint32_t baseBhi = s2u(sBhi);
    const uint32_t baseBlo = s2u(sBlo);

    float acc[2][4][4];
    #pragma unroll
    for (int mt = 0; mt < 2; mt++)
        #pragma unroll
        for (int nt = 0; nt < 4; nt++)
            #pragma unroll
            for (int e = 0; e < 4; e++) acc[mt][nt][e] = 0.0f;

    const int aRow = lane & 15;
    const int aCol = (lane >> 4) * 8;
    const int bRow = lane & 7;
    const int bCol = lane & 8;

    #pragma unroll
    for (int kt = 0; kt < 4; kt++) {
        int k0 = kt * 16;
        uint32_t ah[2][4], al[2][4];
        #pragma unroll
        for (int mt = 0; mt < 2; mt++) {
            uint32_t off = (uint32_t)(((m0 + mt * 16 + aRow) * HSTRIDE + k0 + aCol) * 2);
            ldsm4(ah[mt][0], ah[mt][1], ah[mt][2], ah[mt][3], baseAhi + off);
            ldsm4(al[mt][0], al[mt][1], al[mt][2], al[mt][3], baseAlo + off);
        }
        #pragma unroll
        for (int nt = 0; nt < 4; nt++) {
            uint32_t boff = (uint32_t)(((n0 + nt * 8 + bRow) * HSTRIDE + k0 + bCol) * 2);
            uint32_t bh0, bh1, bl0, bl1;
            ldsm2(bh0, bh1, baseBhi + boff);
            ldsm2(bl0, bl1, baseBlo + boff);
            #pragma unroll
            for (int mt = 0; mt < 2; mt++) {
                mma16816(acc[mt][nt], ah[mt][0], ah[mt][1], ah[mt][2], ah[mt][3], bh0, bh1);
                mma16816(acc[mt][nt], ah[mt][0], ah[mt][1], ah[mt][2], ah[mt][3], bl0, bl1);
                mma16816(acc[mt][nt], al[mt][0], al[mt][1], al[mt][2], al[mt][3], bh0, bh1);
            }
        }
    }

    // Epilogue: D frag -> global (+bias). d0,d1: row groupRow, cols c,c+1;
    // d2,d3: row groupRow+8.
    #pragma unroll
    for (int mt = 0; mt < 2; mt++) {
        int r1 = row0 + m0 + mt * 16 + (lane >> 2);
        #pragma unroll
        for (int nt = 0; nt < 4; nt++) {
            int c = col0 + n0 + nt * 8 + 2 * (lane & 3);
            float b0v = __ldg(&bias[c]);
            float b1v = __ldg(&bias[c + 1]);
            float2 w0 = make_float2(acc[mt][nt][0] + b0v, acc[mt][nt][1] + b1v);
            float2 w1 = make_float2(acc[mt][nt][2] + b0v, acc[mt][nt][3] + b1v);
            *(float2*)&out[(size_t)r1 * VOC + c]       = w0;
            *(float2*)&out[(size_t)(r1 + 8) * VOC + c] = w1;
        }
    }
}

// ===========================================================================
// Launch
// ===========================================================================
extern "C" void kernel_launch(void* const* d_in, const int* in_sizes, int n_in,
                              void* d_out, int out_size)
{
    const int*   idx    = (const int*)  d_in[0];
    const float* tok    = (const float*)d_in[1];
    const float* pos    = (const float*)d_in[2];
    const float* wq     = (const float*)d_in[3];
    const float* wk     = (const float*)d_in[4];
    const float* wv     = (const float*)d_in[5];
    const float* w_proj = (const float*)d_in[6];
    const float* b_proj = (const float*)d_in[7];
    const float* ln1_g  = (const float*)d_in[8];
    const float* ln1_b  = (const float*)d_in[9];
    const float* ln2_g  = (const float*)d_in[10];
    const float* ln2_b  = (const float*)d_in[11];
    const float* w1     = (const float*)d_in[12];
    const float* b1     = (const float*)d_in[13];
    const float* w2     = (const float*)d_in[14];
    const float* b2     = (const float*)d_in[15];
    const float* lnf_g  = (const float*)d_in[16];
    const float* lnf_b  = (const float*)d_in[17];
    const float* w_head = (const float*)d_in[18];
    const float* b_head = (const float*)d_in[19];
    float* out = (float*)d_out;

    cudaFuncSetAttribute(head_mma_k, cudaFuncAttributeMaxDynamicSharedMemorySize, SM_HEAD_BYTES);

    void* sp = nullptr;
    cudaGetSymbolAddress(&sp, g_scratch);
    float* g_x  = (float*)sp;
    float* g_h  = g_x + SZ_XC;
    float* g_q  = g_h + SZ_XC;
    float* g_k  = g_q + SZ_XC;
    float* g_v  = g_k + SZ_XC;
    float* g_o  = g_v + SZ_XC;
    float* g_ff = g_o + SZ_XC;

    void *phhi, *phlo, *pwhi, *pwlo;
    cudaGetSymbolAddress(&phhi, g_hhi);
    cudaGetSymbolAddress(&phlo, g_hlo);
    cudaGetSymbolAddress(&pwhi, g_wthi);
    cudaGetSymbolAddress(&pwlo, g_wtlo);

    // W transpose+convert (independent of the layer stack)
    conv_w_k<<<(VOC*Cn)/256, 256>>>(w_head, (__nv_bfloat16*)pwhi, (__nv_bfloat16*)pwlo);

    embed_ln_k<<<BT/8, 256>>>(idx, tok, pos, ln1_g, ln1_b, g_x, g_h);

    for (int l = 0; l < Ln; l++) {
        qkv_k<<<dim3(1, 128, 3), 128>>>(g_h, wq + l*Cn*Cn, wk + l*Cn*Cn, wv + l*Cn*Cn,
                                        g_q, g_k, g_v);
        attn_kernel<<<Bc*Hn, 256>>>(g_q, g_k, g_v, g_o);
        gemm_k<2><<<dim3(1, 128), 128>>>(g_o, w_proj + l*Cn*Cn, b_proj + l*Cn, g_x,
                                         g_x, g_h, ln2_g + l*Cn, ln2_b + l*Cn, 64, 64);
        gemm_k<1><<<dim3(4, 128), 128>>>(g_h, w1 + l*Cn*DFF, b1 + l*DFF, nullptr,
                                         g_ff, nullptr, nullptr, nullptr, DFF, 64);
        const float* ng = (l < Ln-1) ? ln1_g + (l+1)*Cn : lnf_g;
        const float* nb = (l < Ln-1) ? ln1_b + (l+1)*Cn : lnf_b;
        gemm_k<2><<<dim3(1, 128), 128>>>(g_ff, w2 + l*DFF*Cn, b2 + l*Cn, g_x,
                                         g_x, g_h, ng, nb, 64, 256);
    }

    conv_h_k<<<(BT*Cn)/256, 256>>>(g_h, (__nv_bfloat16*)phhi, (__nv_bfloat16*)phlo);

    head_mma_k<<<dim3(VOC/64, BT/128), 256, SM_HEAD_BYTES>>>(
        (const __nv_bfloat16*)phhi, (const __nv_bfloat16*)phlo,
        (const __nv_bfloat16*)pwhi, (const __nv_bfloat16*)pwlo,
        b_head, out);
}

// round 17
// speedup vs baseline: 2.0513x; 2.0513x over previous
#include <cuda_runtime.h>
#include <cuda_bf16.h>
#include <math_constants.h>
#include <cstdint>

#define Bc   64
#define Tc   256
#define Cn   64
#define Hn   8
#define HSn  8
#define Ln   10
#define DFF  256
#define VOC  8000
#define BT   (Bc*Tc)
#define EPSF 1e-5f

#define SZ_XC (BT*Cn)
#define SZ_FF (BT*DFF)
__device__ float g_scratch[SZ_XC*6 + SZ_FF];
__device__ __nv_bfloat16 g_hhi[BT*Cn];
__device__ __nv_bfloat16 g_hlo[BT*Cn];
__device__ __nv_bfloat16 g_wthi[VOC*Cn];   // transposed: [n][k]
__device__ __nv_bfloat16 g_wtlo[VOC*Cn];

typedef unsigned long long u64;

// ===========================================================================
// mma.sync helpers (plain sm_103 PTX)
// ===========================================================================
__device__ __forceinline__ uint32_t s2u(const void* p){
    uint32_t a;
    asm("{ .reg .u64 t; cvta.to.shared.u64 t, %1; cvt.u32.u64 %0, t; }" : "=r"(a) : "l"(p));
    return a;
}
__device__ __forceinline__ void ldsm4(uint32_t& r0, uint32_t& r1, uint32_t& r2, uint32_t& r3, uint32_t addr){
    asm volatile("ldmatrix.sync.aligned.m8n8.x4.shared.b16 {%0,%1,%2,%3}, [%4];"
        : "=r"(r0), "=r"(r1), "=r"(r2), "=r"(r3) : "r"(addr));
}
__device__ __forceinline__ void ldsm2(uint32_t& r0, uint32_t& r1, uint32_t addr){
    asm volatile("ldmatrix.sync.aligned.m8n8.x2.shared.b16 {%0,%1}, [%2];"
        : "=r"(r0), "=r"(r1) : "r"(addr));
}
__device__ __forceinline__ void ldsm2t(uint32_t& r0, uint32_t& r1, uint32_t addr){
    asm volatile("ldmatrix.sync.aligned.m8n8.x2.trans.shared.b16 {%0,%1}, [%2];"
        : "=r"(r0), "=r"(r1) : "r"(addr));
}
__device__ __forceinline__ void mma16816(float* d, uint32_t a0, uint32_t a1, uint32_t a2, uint32_t a3,
                                         uint32_t b0, uint32_t b1){
    asm volatile("mma.sync.aligned.m16n8k16.row.col.f32.bf16.bf16.f32 "
        "{%0,%1,%2,%3}, {%4,%5,%6,%7}, {%8,%9}, {%0,%1,%2,%3};"
        : "+f"(d[0]), "+f"(d[1]), "+f"(d[2]), "+f"(d[3])
        : "r"(a0), "r"(a1), "r"(a2), "r"(a3), "r"(b0), "r"(b1));
}

// fp32 float4 -> bf16 hi/lo (4 each) stored at elem offset `off`
__device__ __forceinline__ void stg_hilo(__nv_bfloat16* hi, __nv_bfloat16* lo, int off, float4 t){
    __nv_bfloat16 h0 = __float2bfloat16_rn(t.x);
    __nv_bfloat16 h1 = __float2bfloat16_rn(t.y);
    __nv_bfloat16 h2 = __float2bfloat16_rn(t.z);
    __nv_bfloat16 h3 = __float2bfloat16_rn(t.w);
    *(__nv_bfloat162*)(hi + off)     = __halves2bfloat162(h0, h1);
    *(__nv_bfloat162*)(hi + off + 2) = __halves2bfloat162(h2, h3);
    __nv_bfloat16 l0 = __float2bfloat16_rn(t.x - __bfloat162float(h0));
    __nv_bfloat16 l1 = __float2bfloat16_rn(t.y - __bfloat162float(h1));
    __nv_bfloat16 l2 = __float2bfloat16_rn(t.z - __bfloat162float(h2));
    __nv_bfloat16 l3 = __float2bfloat16_rn(t.w - __bfloat162float(h3));
    *(__nv_bfloat162*)(lo + off)     = __halves2bfloat162(l0, l1);
    *(__nv_bfloat162*)(lo + off + 2) = __halves2bfloat162(l2, l3);
}

// ===========================================================================
// Tensor-core layer GEMM: C[M,N] = A[M,K] @ W[K,N] via bf16 hi/lo 3-term.
// Block 256 thr / 8 warps; tile M=128 x N=64; K staged in 64-chunks with
// fp32->bf16 conversion in the staging path. Warp = 16 rows x 64 cols, so a
// row lives in one warp (LN epilogue needs only 2 shfl_xor in 4-lane groups).
// A [m][k] + ldsm4; W [k][n] + ldsm2.trans (canonical row-major B).
// EPI 0: (+bias) store. EPI 1: (+bias) relu. EPI 2: (+bias+res)->Cout, LN->Hout.
// ===========================================================================
#define LSTRIDE 72
#define SM_GEMM_BYTES ((128 + 128 + 64 + 64) * LSTRIDE * 2)   // 55296

template<int KDIM, int EPI>
__device__ __forceinline__ void mma_gemm_body(
    const float* __restrict__ A, const float* __restrict__ W,
    const float* __restrict__ bias, const float* __restrict__ res,
    float* __restrict__ Cout, float* __restrict__ Hout,
    const float* __restrict__ lng, const float* __restrict__ lnb,
    int N, int col0)
{
    extern __shared__ char smraw[];
    __nv_bfloat16* sAhi = (__nv_bfloat16*)smraw;
    __nv_bfloat16* sAlo = sAhi + 128 * LSTRIDE;
    __nv_bfloat16* sBhi = sAhi + 256 * LSTRIDE;
    __nv_bfloat16* sBlo = sAhi + 320 * LSTRIDE;

    const int tid  = threadIdx.x;
    const int row0 = blockIdx.y * 128;
    const int warp = tid >> 5;
    const int lane = tid & 31;
    const int m0   = warp * 16;

    float acc[8][4];
    #pragma unroll
    for (int nt = 0; nt < 8; nt++)
        #pragma unroll
        for (int e = 0; e < 4; e++) acc[nt][e] = 0.0f;

    const uint32_t bAhi = s2u(sAhi), bAlo = s2u(sAlo);
    const uint32_t bBhi = s2u(sBhi), bBlo = s2u(sBlo);

    for (int k0 = 0; k0 < KDIM; k0 += 64) {
        if (KDIM > 64 && k0 != 0) __syncthreads();
        // A chunk: 128 x 64 fp32 -> bf16 hi/lo
        #pragma unroll
        for (int v = 0; v < 8; v++) {
            int i = tid + v * 256;            // 2048 float4
            int r = i >> 4, c4 = (i & 15) * 4;
            float4 t = *(const float4*)&A[(size_t)(row0 + r) * KDIM + k0 + c4];
            stg_hilo(sAhi, sAlo, r * LSTRIDE + c4, t);
        }
        // W chunk: 64 x 64 fp32 -> bf16 hi/lo ([k][n])
        #pragma unroll
        for (int v = 0; v < 4; v++) {
            int i = tid + v * 256;            // 1024 float4
            int r = i >> 4, c4 = (i & 15) * 4;
            float4 t = *(const float4*)&W[(size_t)(k0 + r) * N + col0 + c4];
            stg_hilo(sBhi, sBlo, r * LSTRIDE + c4, t);
        }
        __syncthreads();

        #pragma unroll
        for (int kt = 0; kt < 4; kt++) {
            int kk = kt * 16;
            uint32_t aoff = (uint32_t)(((m0 + (lane & 15)) * LSTRIDE + kk + (lane >> 4) * 8) * 2);
            uint32_t ah[4], al[4];
            ldsm4(ah[0], ah[1], ah[2], ah[3], bAhi + aoff);
            ldsm4(al[0], al[1], al[2], al[3], bAlo + aoff);
            #pragma unroll
            for (int nt = 0; nt < 8; nt++) {
                uint32_t boff = (uint32_t)(((kk + (lane & 15)) * LSTRIDE + nt * 8) * 2);
                uint32_t bh0, bh1, bl0, bl1;
                ldsm2t(bh0, bh1, bBhi + boff);
                ldsm2t(bl0, bl1, bBlo + boff);
                mma16816(acc[nt], ah[0], ah[1], ah[2], ah[3], bh0, bh1);
                mma16816(acc[nt], ah[0], ah[1], ah[2], ah[3], bl0, bl1);
                mma16816(acc[nt], al[0], al[1], al[2], al[3], bh0, bh1);
            }
        }
    }

    // --------------------------- epilogue ---------------------------------
    const int ra = row0 + m0 + (lane >> 2);   // rows ra, ra+8
    const int cl = 2 * (lane & 3);

    float va[16], vb[16];                     // [nt*2+j]: col nt*8+cl+j
    #pragma unroll
    for (int nt = 0; nt < 8; nt++) {
        float b0 = 0.f, b1 = 0.f;
        if (EPI != 0 || bias) {               // qkv passes nullptr
            if (bias) { b0 = __ldg(&bias[col0 + nt*8 + cl]); b1 = __ldg(&bias[col0 + nt*8 + cl + 1]); }
        }
        va[nt*2]   = acc[nt][0] + b0;
        va[nt*2+1] = acc[nt][1] + b1;
        vb[nt*2]   = acc[nt][2] + b0;
        vb[nt*2+1] = acc[nt][3] + b1;
    }

    if (EPI == 1) {
        #pragma unroll
        for (int i = 0; i < 16; i++) { va[i] = fmaxf(va[i], 0.f); vb[i] = fmaxf(vb[i], 0.f); }
    }

    if (EPI == 2) {                           // N == 64, col0 == 0
        #pragma unroll
        for (int nt = 0; nt < 8; nt++) {
            float2 r1 = *(const float2*)&res[(size_t)ra * 64 + nt*8 + cl];
            float2 r2 = *(const float2*)&res[(size_t)(ra + 8) * 64 + nt*8 + cl];
            va[nt*2] += r1.x; va[nt*2+1] += r1.y;
            vb[nt*2] += r2.x; vb[nt*2+1] += r2.y;
        }
        float s1a = 0.f, s2a = 0.f, s1b = 0.f, s2b = 0.f;
        #pragma unroll
        for (int i = 0; i < 16; i++) {
            s1a += va[i]; s2a += va[i]*va[i];
            s1b += vb[i]; s2b += vb[i]*vb[i];
        }
        #pragma unroll
        for (int o = 1; o < 4; o <<= 1) {
            s1a += __shfl_xor_sync(0xFFFFFFFFu, s1a, o);
            s2a += __shfl_xor_sync(0xFFFFFFFFu, s2a, o);
            s1b += __shfl_xor_sync(0xFFFFFFFFu, s1b, o);
            s2b += __shfl_xor_sync(0xFFFFFFFFu, s2b, o);
        }
        float mua = s1a * (1.f/64.f), mub = s1b * (1.f/64.f);
        float rsa = rsqrtf(s2a * (1.f/64.f) - mua*mua + EPSF);
        float rsb = rsqrtf(s2b * (1.f/64.f) - mub*mub + EPSF);
        #pragma unroll
        for (int nt = 0; nt < 8; nt++) {
            int c = nt*8 + cl;
            *(float2*)&Cout[(size_t)ra * 64 + c]       = make_float2(va[nt*2], va[nt*2+1]);
            *(float2*)&Cout[(size_t)(ra + 8) * 64 + c] = make_float2(vb[nt*2], vb[nt*2+1]);
            float g0 = __ldg(&lng[c]), g1 = __ldg(&lng[c+1]);
            float e0 = __ldg(&lnb[c]), e1 = __ldg(&lnb[c+1]);
            *(float2*)&Hout[(size_t)ra * 64 + c] =
                make_float2((va[nt*2]-mua)*rsa*g0 + e0, (va[nt*2+1]-mua)*rsa*g1 + e1);
            *(float2*)&Hout[(size_t)(ra + 8) * 64 + c] =
                make_float2((vb[nt*2]-mub)*rsb*g0 + e0, (vb[nt*2+1]-mub)*rsb*g1 + e1);
        }
    } else {
        #pragma unroll
        for (int nt = 0; nt < 8; nt++) {
            int c = col0 + nt*8 + cl;
            *(float2*)&Cout[(size_t)ra * N + c]       = make_float2(va[nt*2], va[nt*2+1]);
            *(float2*)&Cout[(size_t)(ra + 8) * N + c] = make_float2(vb[nt*2], vb[nt*2+1]);
        }
    }
}

__global__ void __launch_bounds__(256)
qkv_mma_k(const float* __restrict__ A,
          const float* __restrict__ wq, const float* __restrict__ wk, const float* __restrict__ wv,
          float* __restrict__ qo, float* __restrict__ ko, float* __restrict__ vo)
{
    const float* W = (blockIdx.z == 0) ? wq : (blockIdx.z == 1) ? wk : wv;
    float*       O = (blockIdx.z == 0) ? qo : (blockIdx.z == 1) ? ko : vo;
    mma_gemm_body<64, 0>(A, W, nullptr, nullptr, O, nullptr, nullptr, nullptr, 64, 0);
}

__global__ void __launch_bounds__(256)
proj_mma_k(const float* __restrict__ A, const float* __restrict__ W,
           const float* __restrict__ bias, const float* __restrict__ res,
           float* __restrict__ Cout, float* __restrict__ Hout,
           const float* __restrict__ lng, const float* __restrict__ lnb)
{
    mma_gemm_body<64, 2>(A, W, bias, res, Cout, Hout, lng, lnb, 64, 0);
}

__global__ void __launch_bounds__(256)
ff1_mma_k(const float* __restrict__ A, const float* __restrict__ W,
          const float* __restrict__ bias, float* __restrict__ Cout)
{
    mma_gemm_body<64, 1>(A, W, bias, nullptr, Cout, nullptr, nullptr, nullptr, DFF, blockIdx.x * 64);
}

__global__ void __launch_bounds__(256)
ff2_mma_k(const float* __restrict__ A, const float* __restrict__ W,
          const float* __restrict__ bias, const float* __restrict__ res,
          float* __restrict__ Cout, float* __restrict__ Hout,
          const float* __restrict__ lng, const float* __restrict__ lnb)
{
    mma_gemm_body<256, 2>(A, W, bias, res, Cout, Hout, lng, lnb, 64, 0);
}

// ===========================================================================
// Embedding + first LayerNorm (R3)
// ===========================================================================
__global__ void __launch_bounds__(256)
embed_ln_k(const int* __restrict__ idx, const float* __restrict__ tok,
           const float* __restrict__ pos, const float* __restrict__ g,
           const float* __restrict__ b, float* __restrict__ x, float* __restrict__ h)
{
    int row  = blockIdx.x * 8 + (threadIdx.x >> 5);
    int lane = threadIdx.x & 31;
    int t    = row & (Tc - 1);
    int tr   = idx[row];
    float v0 = tok[tr*Cn + lane]      + pos[t*Cn + lane];
    float v1 = tok[tr*Cn + lane + 32] + pos[t*Cn + lane + 32];
    float sum = v0 + v1;
    #pragma unroll
    for (int o = 16; o; o >>= 1) sum += __shfl_xor_sync(0xFFFFFFFFu, sum, o);
    float mu = sum * (1.f/64.f);
    float d0 = v0 - mu, d1 = v1 - mu;
    float vs = d0*d0 + d1*d1;
    #pragma unroll
    for (int o = 16; o; o >>= 1) vs += __shfl_xor_sync(0xFFFFFFFFu, vs, o);
    float r = rsqrtf(vs * (1.f/64.f) + EPSF);
    x[row*Cn + lane]      = v0;
    x[row*Cn + lane + 32] = v1;
    h[row*Cn + lane]      = d0*r*g[lane]    + b[lane];
    h[row*Cn + lane + 32] = d1*r*g[lane+32] + b[lane+32];
}

// ===========================================================================
// Attention v2 (R13 winner): block per (b,h), 256 threads = 256 query rows.
// ===========================================================================
__global__ void __launch_bounds__(256)
attn_kernel(const float* __restrict__ q, const float* __restrict__ kk,
            const float* __restrict__ vv, float* __restrict__ oo)
{
    int bh = blockIdx.x;
    int b  = bh >> 3;
    int h  = bh & 7;
    __shared__ float ks[Tc][8];
    __shared__ float vs[Tc][8];

    int tid  = threadIdx.x;
    int base = b * Tc * Cn + h * HSn;

    {
        float4 a = *(const float4*)&kk[base + tid*Cn];
        float4 c = *(const float4*)&kk[base + tid*Cn + 4];
        *(float4*)&ks[tid][0] = a; *(float4*)&ks[tid][4] = c;
        a = *(const float4*)&vv[base + tid*Cn];
        c = *(const float4*)&vv[base + tid*Cn + 4];
        *(float4*)&vs[tid][0] = a; *(float4*)&vs[tid][4] = c;
    }
    __syncthreads();

    const int row = tid;
    float qd[8];
    {
        float4 a = *(const float4*)&q[base + row*Cn];
        float4 c = *(const float4*)&q[base + row*Cn + 4];
        qd[0]=a.x*0.125f; qd[1]=a.y*0.125f; qd[2]=a.z*0.125f; qd[3]=a.w*0.125f;
        qd[4]=c.x*0.125f; qd[5]=c.y*0.125f; qd[6]=c.z*0.125f; qd[7]=c.w*0.125f;
    }

    float s = 0.0f;
    float o[8];
    #pragma unroll
    for (int d = 0; d < 8; d++) o[d] = 0.0f;

    #pragma unroll 2
    for (int j = 0; j <= row; j++) {
        float4 ka = *(const float4*)&ks[j][0];
        float4 kb = *(const float4*)&ks[j][4];
        float sc = qd[0]*ka.x;
        sc = fmaf(qd[1], ka.y, sc);
        sc = fmaf(qd[2], ka.z, sc);
        sc = fmaf(qd[3], ka.w, sc);
        sc = fmaf(qd[4], kb.x, sc);
        sc = fmaf(qd[5], kb.y, sc);
        sc = fmaf(qd[6], kb.z, sc);
        sc = fmaf(qd[7], kb.w, sc);
        float e = __expf(sc);
        s += e;
        float4 va = *(const float4*)&vs[j][0];
        float4 vb = *(const float4*)&vs[j][4];
        o[0] = fmaf(e, va.x, o[0]);
        o[1] = fmaf(e, va.y, o[1]);
        o[2] = fmaf(e, va.z, o[2]);
        o[3] = fmaf(e, va.w, o[3]);
        o[4] = fmaf(e, vb.x, o[4]);
        o[5] = fmaf(e, vb.y, o[5]);
        o[6] = fmaf(e, vb.z, o[6]);
        o[7] = fmaf(e, vb.w, o[7]);
    }

    float inv = 1.0f / s;
    *(float4*)&oo[base + row*Cn]     = make_float4(o[0]*inv, o[1]*inv, o[2]*inv, o[3]*inv);
    *(float4*)&oo[base + row*Cn + 4] = make_float4(o[4]*inv, o[5]*inv, o[6]*inv, o[7]*inv);
}

// ===========================================================================
// bf16 hi/lo converts for the tensor-core head
// ===========================================================================
__global__ void __launch_bounds__(256)
conv_h_k(const float* __restrict__ h, __nv_bfloat16* __restrict__ hhi,
         __nv_bfloat16* __restrict__ hlo)
{
    int i = blockIdx.x * 256 + threadIdx.x;
    float x = h[i];
    __nv_bfloat16 hb = __float2bfloat16_rn(x);
    hhi[i] = hb;
    hlo[i] = __float2bfloat16_rn(x - __bfloat162float(hb));
}

__global__ void __launch_bounds__(256)
conv_w_k(const float* __restrict__ w, __nv_bfloat16* __restrict__ whi,
         __nv_bfloat16* __restrict__ wlo)
{
    int i = blockIdx.x * 256 + threadIdx.x;   // over VOC*64
    int n = i >> 6;
    int k = i & 63;
    float x = w[k * VOC + n];
    __nv_bfloat16 hb = __float2bfloat16_rn(x);
    whi[i] = hb;
    wlo[i] = __float2bfloat16_rn(x - __bfloat162float(hb));
}

// ===========================================================================
// Tensor-core head GEMM (R13 version, passed). M=128 x N=64, K=64 resident.
// ===========================================================================
#define HSTRIDE 72
#define SM_HEAD_BYTES ((128 + 128 + 64 + 64) * HSTRIDE * 2)   // 55296

__global__ void __launch_bounds__(256)
head_mma_k(const __nv_bfloat16* __restrict__ ahi, const __nv_bfloat16* __restrict__ alo,
           const __nv_bfloat16* __restrict__ bhi, const __nv_bfloat16* __restrict__ blo,
           const float* __restrict__ bias, float* __restrict__ out)
{
    extern __shared__ char smraw[];
    __nv_bfloat16* sm = (__nv_bfloat16*)smraw;
    __nv_bfloat16* sAhi = sm;
    __nv_bfloat16* sAlo = sm + 128 * HSTRIDE;
    __nv_bfloat16* sBhi = sm + 256 * HSTRIDE;
    __nv_bfloat16* sBlo = sm + 320 * HSTRIDE;

    const int tid  = threadIdx.x;
    const int row0 = blockIdx.y * 128;
    const int col0 = blockIdx.x * 64;

    #pragma unroll
    for (int v = 0; v < 4; v++) {
        int i = tid + v * 256;
        int r = i >> 3, c = (i & 7) * 8;
        *(uint4*)&sAhi[r * HSTRIDE + c] = *(const uint4*)&ahi[(row0 + r) * 64 + c];
        *(uint4*)&sAlo[r * HSTRIDE + c] = *(const uint4*)&alo[(row0 + r) * 64 + c];
    }
    #pragma unroll
    for (int v = 0; v < 2; v++) {
        int i = tid + v * 256;
        int r = i >> 3, c = (i & 7) * 8;
        *(uint4*)&sBhi[r * HSTRIDE + c] = *(const uint4*)&bhi[(col0 + r) * 64 + c];
        *(uint4*)&sBlo[r * HSTRIDE + c] = *(const uint4*)&blo[(col0 + r) * 64 + c];
    }
    __syncthreads();

    const int warp = tid >> 5;
    const int lane = tid & 31;
    const int m0 = (warp & 3) * 32;
    const int n0 = (warp >> 2) * 32;

    const uint32_t baseAhi = s2u(sAhi);
    const uint32_t baseAlo = s2u(sAlo);
    const uint32_t baseBhi = s2u(sBhi);
    const uint32_t baseBlo = s2u(sBlo);

    float acc[2][4][4];
    #pragma unroll
    for (int mt = 0; mt < 2; mt++)
        #pragma unroll
        for (int nt = 0; nt < 4; nt++)
            #pragma unroll
            for (int e = 0; e < 4; e++) acc[mt][nt][e] = 0.0f;

    const int aRow = lane & 15;
    const int aCol = (lane >> 4) * 8;
    const int bRow = lane & 7;
    const int bCol = lane & 8;

    #pragma unroll
    for (int kt = 0; kt < 4; kt++) {
        int k0 = kt * 16;
        uint32_t ah[2][4], al[2][4];
        #pragma unroll
        for (int mt = 0; mt < 2; mt++) {
            uint32_t off = (uint32_t)(((m0 + mt * 16 + aRow) * HSTRIDE + k0 + aCol) * 2);
            ldsm4(ah[mt][0], ah[mt][1], ah[mt][2], ah[mt][3], baseAhi + off);
            ldsm4(al[mt][0], al[mt][1], al[mt][2], al[mt][3], baseAlo + off);
        }
        #pragma unroll
        for (int nt = 0; nt < 4; nt++) {
            uint32_t boff = (uint32_t)(((n0 + nt * 8 + bRow) * HSTRIDE + k0 + bCol) * 2);
            uint32_t bh0, bh1, bl0, bl1;
            ldsm2(bh0, bh1, baseBhi + boff);
            ldsm2(bl0, bl1, baseBlo + boff);
            #pragma unroll
            for (int mt = 0; mt < 2; mt++) {
                mma16816(acc[mt][nt], ah[mt][0], ah[mt][1], ah[mt][2], ah[mt][3], bh0, bh1);
                mma16816(acc[mt][nt], ah[mt][0], ah[mt][1], ah[mt][2], ah[mt][3], bl0, bl1);
                mma16816(acc[mt][nt], al[mt][0], al[mt][1], al[mt][2], al[mt][3], bh0, bh1);
            }
        }
    }

    #pragma unroll
    for (int mt = 0; mt < 2; mt++) {
        int r1 = row0 + m0 + mt * 16 + (lane >> 2);
        #pragma unroll
        for (int nt = 0; nt < 4; nt++) {
            int c = col0 + n0 + nt * 8 + 2 * (lane & 3);
            float b0v = __ldg(&bias[c]);
            float b1v = __ldg(&bias[c + 1]);
            float2 w0 = make_float2(acc[mt][nt][0] + b0v, acc[mt][nt][1] + b1v);
            float2 w1 = make_float2(acc[mt][nt][2] + b0v, acc[mt][nt][3] + b1v);
            *(float2*)&out[(size_t)r1 * VOC + c]       = w0;
            *(float2*)&out[(size_t)(r1 + 8) * VOC + c] = w1;
        }
    }
}

// ===========================================================================
// Launch
// ===========================================================================
extern "C" void kernel_launch(void* const* d_in, const int* in_sizes, int n_in,
                              void* d_out, int out_size)
{
    const int*   idx    = (const int*)  d_in[0];
    const float* tok    = (const float*)d_in[1];
    const float* pos    = (const float*)d_in[2];
    const float* wq     = (const float*)d_in[3];
    const float* wk     = (const float*)d_in[4];
    const float* wv     = (const float*)d_in[5];
    const float* w_proj = (const float*)d_in[6];
    const float* b_proj = (const float*)d_in[7];
    const float* ln1_g  = (const float*)d_in[8];
    const float* ln1_b  = (const float*)d_in[9];
    const float* ln2_g  = (const float*)d_in[10];
    const float* ln2_b  = (const float*)d_in[11];
    const float* w1     = (const float*)d_in[12];
    const float* b1     = (const float*)d_in[13];
    const float* w2     = (const float*)d_in[14];
    const float* b2     = (const float*)d_in[15];
    const float* lnf_g  = (const float*)d_in[16];
    const float* lnf_b  = (const float*)d_in[17];
    const float* w_head = (const float*)d_in[18];
    const float* b_head = (const float*)d_in[19];
    float* out = (float*)d_out;

    cudaFuncSetAttribute(head_mma_k, cudaFuncAttributeMaxDynamicSharedMemorySize, SM_HEAD_BYTES);
    cudaFuncSetAttribute(qkv_mma_k,  cudaFuncAttributeMaxDynamicSharedMemorySize, SM_GEMM_BYTES);
    cudaFuncSetAttribute(proj_mma_k, cudaFuncAttributeMaxDynamicSharedMemorySize, SM_GEMM_BYTES);
    cudaFuncSetAttribute(ff1_mma_k,  cudaFuncAttributeMaxDynamicSharedMemorySize, SM_GEMM_BYTES);
    cudaFuncSetAttribute(ff2_mma_k,  cudaFuncAttributeMaxDynamicSharedMemorySize, SM_GEMM_BYTES);

    void* sp = nullptr;
    cudaGetSymbolAddress(&sp, g_scratch);
    float* g_x  = (float*)sp;
    float* g_h  = g_x + SZ_XC;
    float* g_q  = g_h + SZ_XC;
    float* g_k  = g_q + SZ_XC;
    float* g_v  = g_k + SZ_XC;
    float* g_o  = g_v + SZ_XC;
    float* g_ff = g_o + SZ_XC;

    void *phhi, *phlo, *pwhi, *pwlo;
    cudaGetSymbolAddress(&phhi, g_hhi);
    cudaGetSymbolAddress(&phlo, g_hlo);
    cudaGetSymbolAddress(&pwhi, g_wthi);
    cudaGetSymbolAddress(&pwlo, g_wtlo);

    conv_w_k<<<(VOC*Cn)/256, 256>>>(w_head, (__nv_bfloat16*)pwhi, (__nv_bfloat16*)pwlo);

    embed_ln_k<<<BT/8, 256>>>(idx, tok, pos, ln1_g, ln1_b, g_x, g_h);

    for (int l = 0; l < Ln; l++) {
        qkv_mma_k<<<dim3(1, BT/128, 3), 256, SM_GEMM_BYTES>>>(
            g_h, wq + l*Cn*Cn, wk + l*Cn*Cn, wv + l*Cn*Cn, g_q, g_k, g_v);
        attn_kernel<<<Bc*Hn, 256>>>(g_q, g_k, g_v, g_o);
        proj_mma_k<<<dim3(1, BT/128), 256, SM_GEMM_BYTES>>>(
            g_o, w_proj + l*Cn*Cn, b_proj + l*Cn, g_x, g_x, g_h,
            ln2_g + l*Cn, ln2_b + l*Cn);
        ff1_mma_k<<<dim3(4, BT/128), 256, SM_GEMM_BYTES>>>(
            g_h, w1 + l*Cn*DFF, b1 + l*DFF, g_ff);
        const float* ng = (l < Ln-1) ? ln1_g + (l+1)*Cn : lnf_g;
        const float* nb = (l < Ln-1) ? ln1_b + (l+1)*Cn : lnf_b;
        ff2_mma_k<<<dim3(1, BT/128), 256, SM_GEMM_BYTES>>>(
            g_ff, w2 + l*DFF*Cn, b2 + l*Cn, g_x, g_x, g_h, ng, nb);
    }

    conv_h_k<<<(BT*Cn)/256, 256>>>(g_h, (__nv_bfloat16*)phhi, (__nv_bfloat16*)phlo);

    head_mma_k<<<dim3(VOC/64, BT/128), 256, SM_HEAD_BYTES>>>(
        (const __nv_bfloat16*)phhi, (const __nv_bfloat16*)phlo,
        (const __nv_bfloat16*)pwhi, (const __nv_bfloat16*)pwlo,
        b_head, out);
}